// round 16
// baseline (speedup 1.0000x reference)
#include <cuda_runtime.h>
#include <cstdint>

// Collapsed SimpleAttention: out[b,k] = (mean_s x[b,s,:]) @ Wv[:,k] + bv[k]
// (softmax over the query axis => sum_q att[b,q,s] = 1 => Q/K/att cancel
//  exactly under the mean-pool).
//
// R15 = R14's TMA stage-1 RE-TUNED: chunk 2 rows -> 4 rows (16 KB).
//   * per-block chunk count 14 -> 7: halves the per-chunk serialization
//     (mbarrier TRYWAIT ~90cyc + syncthreads + refill issue) that sank R14.
//   * outstanding bytes per block double (16-32 KB steady state).
// Tail (counter wait + Phase A + Phase B) is R10 verbatim (best: 17.0us).

#define BB     8
#define SS     2048
#define DD     1024
#define DKK    512
#define NCHUNK 74                       // stage-1 blocks per batch
#define TOTB   (NCHUNK * BB)            // 592 = 4 * 148 (one balanced wave)
#define CROWS  4                        // rows per TMA chunk (16 KB)

__device__ float g_partial[BB * NCHUNK * DD];   // [b][chunk][d]
__device__ unsigned g_cb[BB] = {0};             // per-batch arrival counters
__device__ unsigned g_done = 0;

__device__ __forceinline__ void spin_until(unsigned* ctr, unsigned target) {
    const volatile unsigned* p = (const volatile unsigned*)ctr;
    while (*p != target) __nanosleep(32);
}

__device__ __forceinline__ uint32_t smem_u32(const void* p) {
    uint32_t a;
    asm("{ .reg .u64 tmp; cvta.to.shared.u64 tmp, %1; cvt.u32.u64 %0, tmp; }"
        : "=r"(a) : "l"(p));
    return a;
}

__device__ __forceinline__ void mbar_init(uint32_t addr, uint32_t count) {
    asm volatile("mbarrier.init.shared.b64 [%0], %1;"
                 :: "r"(addr), "r"(count) : "memory");
}

__device__ __forceinline__ void mbar_expect_tx(uint32_t addr, uint32_t bytes) {
    asm volatile("mbarrier.arrive.expect_tx.shared.b64 _, [%0], %1;"
                 :: "r"(addr), "r"(bytes) : "memory");
}

__device__ __forceinline__ void mbar_wait(uint32_t addr, uint32_t parity) {
    asm volatile(
        "{\n\t"
        ".reg .pred P;\n"
        "WAIT_%=:\n\t"
        "mbarrier.try_wait.parity.acquire.cta.shared::cta.b64 P, [%0], %1, 0x989680;\n\t"
        "@P bra DONE_%=;\n\t"
        "bra WAIT_%=;\n\t"
        "DONE_%=:\n\t"
        "}"
        :: "r"(addr), "r"(parity) : "memory");
}

__device__ __forceinline__ void bulk_copy_g2s(uint32_t dst_smem,
                                              const void* src_gmem,
                                              uint32_t bytes,
                                              uint32_t mbar_addr) {
    asm volatile(
        "cp.async.bulk.shared::cluster.global.mbarrier::complete_tx::bytes "
        "[%0], [%1], %2, [%3];"
        :: "r"(dst_smem), "l"(src_gmem), "r"(bytes), "r"(mbar_addr)
        : "memory");
}

__global__ void __launch_bounds__(256, 4)
fused_kernel(const float* __restrict__ x,
             const float* __restrict__ Wv,
             const float* __restrict__ bv,
             float* __restrict__ out) {
    __shared__ __align__(128) float buf[2][CROWS * DD];   // 2 x 16 KB
    __shared__ __align__(8) uint64_t mbar[2];
    __shared__ float xbs[DD];           // xbar for this block's batch (tail)
    __shared__ float red[8][64];        // GEMM slice-reduce (tail)

    const int j = blockIdx.x;           // 0..73
    const int b = blockIdx.y;           // 0..7
    const int t = threadIdx.x;

    // ============ Stage 1: column sum of x via TMA bulk pipeline ===========
    {
        const int r0 = (j * SS) / NCHUNK;
        const int r1 = ((j + 1) * SS) / NCHUNK;
        const int n  = r1 - r0;                     // 27 or 28 rows
        const int nch = (n + CROWS - 1) / CROWS;    // 7 chunks

        const float* gb = x + (size_t)(b * SS + r0) * DD;
        const uint32_t mb[2] = { smem_u32(&mbar[0]), smem_u32(&mbar[1]) };
        const uint32_t bufaddr[2] = { smem_u32(&buf[0][0]), smem_u32(&buf[1][0]) };

        if (t == 0) {
            mbar_init(mb[0], 1);
            mbar_init(mb[1], 1);
        }
        asm volatile("fence.proxy.async.shared::cta;" ::: "memory");
        __syncthreads();

        // Prime both buffers (chunks 0 and 1)
        if (t == 0) {
#pragma unroll
            for (int c = 0; c < 2; c++) {
                if (c < nch) {
                    const int rc = (n - CROWS * c) < CROWS ? (n - CROWS * c) : CROWS;
                    const uint32_t bytes = (uint32_t)rc * DD * 4u;
                    mbar_expect_tx(mb[c], bytes);
                    bulk_copy_g2s(bufaddr[c], gb + (size_t)(CROWS * c) * DD,
                                  bytes, mb[c]);
                }
            }
        }

        float4 a0 = make_float4(0.f, 0.f, 0.f, 0.f);
        float4 a1 = make_float4(0.f, 0.f, 0.f, 0.f);
        float4 a2 = make_float4(0.f, 0.f, 0.f, 0.f);
        float4 a3 = make_float4(0.f, 0.f, 0.f, 0.f);

        for (int c = 0; c < nch; c++) {
            const int bi = c & 1;
            mbar_wait(mb[bi], (uint32_t)((c >> 1) & 1));

            const int rc = (n - CROWS * c) < CROWS ? (n - CROWS * c) : CROWS;
            // thread t reads row r at float4 index t + r*(DD/4)
            const float4* bp = reinterpret_cast<const float4*>(&buf[bi][0]) + t;
            {
                const float4 v0 = bp[0 * (DD / 4)];
                const float4 v1 = bp[1 * (DD / 4)];
                const float4 v2 = bp[2 * (DD / 4)];
                a0.x += v0.x; a0.y += v0.y; a0.z += v0.z; a0.w += v0.w;
                a1.x += v1.x; a1.y += v1.y; a1.z += v1.z; a1.w += v1.w;
                a2.x += v2.x; a2.y += v2.y; a2.z += v2.z; a2.w += v2.w;
                if (rc > 3) {
                    const float4 v3 = bp[3 * (DD / 4)];
                    a3.x += v3.x; a3.y += v3.y; a3.z += v3.z; a3.w += v3.w;
                }
            }
            __syncthreads();            // all reads done before refill

            if (t == 0 && c + 2 < nch) {
                const int c2 = c + 2;
                const int rc2 = (n - CROWS * c2) < CROWS ? (n - CROWS * c2) : CROWS;
                const uint32_t bytes = (uint32_t)rc2 * DD * 4u;
                mbar_expect_tx(mb[bi], bytes);
                bulk_copy_g2s(bufaddr[bi], gb + (size_t)(CROWS * c2) * DD,
                              bytes, mb[bi]);
            }
        }
        a0.x += a1.x; a0.y += a1.y; a0.z += a1.z; a0.w += a1.w;
        a2.x += a3.x; a2.y += a3.y; a2.z += a3.z; a2.w += a3.w;
        a0.x += a2.x; a0.y += a2.y; a0.z += a2.z; a0.w += a2.w;

        *reinterpret_cast<float4*>(
            g_partial + ((size_t)(b * NCHUNK + j)) * DD + t * 4) = a0;
    }
    __syncthreads();
    __threadfence();                    // release partials
    if (t == 0) atomicAdd(&g_cb[b], 1u);

    if (j >= 8) return;                 // 528 blocks done; 64 continue

    // =============== Wait for THIS batch's 74 partials only ================
    if (t == 0) spin_until(&g_cb[b], NCHUNK);
    __syncthreads();
    __threadfence();                    // acquire

    const int ktile = j;                // k range [64*ktile, 64*ktile+64)
    const int kbase = ktile * 64;

    // ========= Phase A: xbar reduce, 16 loads in flight ====================
    {
        const float4* p = reinterpret_cast<const float4*>(
            g_partial + (size_t)(b * NCHUNK) * DD) + t;
        const size_t cs = DD / 4;

        float4 a0 = make_float4(0.f, 0.f, 0.f, 0.f);
        float4 a1 = make_float4(0.f, 0.f, 0.f, 0.f);
        float4 a2 = make_float4(0.f, 0.f, 0.f, 0.f);
        float4 a3 = make_float4(0.f, 0.f, 0.f, 0.f);
        int c = 0;
        for (; c + 16 <= NCHUNK; c += 16) {
            float4 v[16];
#pragma unroll
            for (int i = 0; i < 16; i++)
                v[i] = p[(size_t)(c + i) * cs];
#pragma unroll
            for (int i = 0; i < 16; i += 4) {
                a0.x += v[i+0].x; a0.y += v[i+0].y; a0.z += v[i+0].z; a0.w += v[i+0].w;
                a1.x += v[i+1].x; a1.y += v[i+1].y; a1.z += v[i+1].z; a1.w += v[i+1].w;
                a2.x += v[i+2].x; a2.y += v[i+2].y; a2.z += v[i+2].z; a2.w += v[i+2].w;
                a3.x += v[i+3].x; a3.y += v[i+3].y; a3.z += v[i+3].z; a3.w += v[i+3].w;
            }
        }
        for (; c + 8 <= NCHUNK; c += 8) {
            float4 v[8];
#pragma unroll
            for (int i = 0; i < 8; i++)
                v[i] = p[(size_t)(c + i) * cs];
#pragma unroll
            for (int i = 0; i < 8; i += 4) {
                a0.x += v[i+0].x; a0.y += v[i+0].y; a0.z += v[i+0].z; a0.w += v[i+0].w;
                a1.x += v[i+1].x; a1.y += v[i+1].y; a1.z += v[i+1].z; a1.w += v[i+1].w;
                a2.x += v[i+2].x; a2.y += v[i+2].y; a2.z += v[i+2].z; a2.w += v[i+2].w;
                a3.x += v[i+3].x; a3.y += v[i+3].y; a3.z += v[i+3].z; a3.w += v[i+3].w;
            }
        }
        for (; c < NCHUNK; c++) {
            const float4 v = p[(size_t)c * cs];
            a0.x += v.x; a0.y += v.y; a0.z += v.z; a0.w += v.w;
        }
        a0.x += a1.x; a0.y += a1.y; a0.z += a1.z; a0.w += a1.w;
        a2.x += a3.x; a2.y += a3.y; a2.z += a3.z; a2.w += a3.w;
        a0.x += a2.x; a0.y += a2.y; a0.z += a2.z; a0.w += a2.w;

        const float inv = 1.0f / (float)SS;
        a0.x *= inv; a0.y *= inv; a0.z *= inv; a0.w *= inv;
        reinterpret_cast<float4*>(xbs)[t] = a0;
    }
    __syncthreads();

    // ===== Phase B: thread owns a k-pair + 128-d slice; 4 load rounds ======
    {
        const int kp  = (t & 31) * 2;   // k pair within tile (0,2,..,62)
        const int dsl = t >> 5;         // 0..7, 128 d each
        const int d0  = dsl * 128;

        float2 c0 = make_float2(0.f, 0.f);
        float2 c1 = make_float2(0.f, 0.f);
        float2 c2 = make_float2(0.f, 0.f);
        float2 c3 = make_float2(0.f, 0.f);
#pragma unroll
        for (int g = 0; g < 4; g++) {
            const int dg = d0 + g * 32;
            float2 w[32];
#pragma unroll
            for (int i = 0; i < 32; i++)
                w[i] = *reinterpret_cast<const float2*>(
                    Wv + (size_t)(dg + i) * DKK + kbase + kp);
#pragma unroll
            for (int i = 0; i < 32; i += 4) {
                const float x0 = xbs[dg + i + 0];
                const float x1 = xbs[dg + i + 1];
                const float x2 = xbs[dg + i + 2];
                const float x3 = xbs[dg + i + 3];
                c0.x += w[i+0].x * x0; c0.y += w[i+0].y * x0;
                c1.x += w[i+1].x * x1; c1.y += w[i+1].y * x1;
                c2.x += w[i+2].x * x2; c2.y += w[i+2].y * x2;
                c3.x += w[i+3].x * x3; c3.y += w[i+3].y * x3;
            }
        }
        red[dsl][kp]     = (c0.x + c1.x) + (c2.x + c3.x);
        red[dsl][kp + 1] = (c0.y + c1.y) + (c2.y + c3.y);
    }
    __syncthreads();

    if (t < 64) {
        float s = bv[kbase + t];
#pragma unroll
        for (int i = 0; i < 8; i++)
            s += red[i][t];
        out[(size_t)b * DKK + kbase + t] = s;
    }

    // ================= Counter reset (last consumer block) =================
    __syncthreads();
    if (t == 0) {
        const unsigned old = atomicAdd(&g_done, 1u);
        if (old == 63u) {               // all 64 consumer blocks finished
#pragma unroll
            for (int i = 0; i < BB; i++) g_cb[i] = 0;
            g_done = 0;
            __threadfence();
        }
    }
}

// ---------------------------------------------------------------------------
// Inputs (metadata order): x, Wq, bq, Wk, bk, Wv, bv
// ---------------------------------------------------------------------------
extern "C" void kernel_launch(void* const* d_in, const int* in_sizes, int n_in,
                              void* d_out, int out_size) {
    const float* x  = (const float*)d_in[0];
    const float* Wv = (const float*)d_in[5];
    const float* bv = (const float*)d_in[6];
    float* out = (float*)d_out;

    fused_kernel<<<dim3(NCHUNK, BB), 256>>>(x, Wv, bv, out);
}

// round 17
// speedup vs baseline: 1.1345x; 1.1345x over previous
#include <cuda_runtime.h>

// Collapsed SimpleAttention: out[b,k] = (mean_s x[b,s,:]) @ Wv[:,k] + bv[k]
// (softmax over the query axis => sum_q att[b,q,s] = 1 => Q/K/att cancel
//  exactly under the mean-pool).
//
// R16 = R10 (best: 17.0us) with ONE change: NCHUNK 74 -> 37.
//   Grid (37,8) = 296 blocks = exactly 2 CTAs/SM (was 4). Per the B300
//   multi-CTA spread model, oe*MLP_p1 drops 32 -> 16 = the contention knee,
//   collapsing cross-CTA L1tex straggler spread to the ~1.10 floor.
//   Bonus: Phase A reduces 37 partials instead of 74.
// TMA (R14/R15) and all overlap schemes are falsified; LDG 8-deep stands.

#define BB     8
#define SS     2048
#define DD     1024
#define DKK    512
#define NCHUNK 37                       // stage-1 blocks per batch
#define TOTB   (NCHUNK * BB)            // 296 = 2 * 148 (one balanced wave)

__device__ float g_partial[BB * NCHUNK * DD];   // [b][chunk][d]
__device__ unsigned g_cb[BB] = {0};             // per-batch arrival counters
__device__ unsigned g_done = 0;

__device__ __forceinline__ void spin_until(unsigned* ctr, unsigned target) {
    const volatile unsigned* p = (const volatile unsigned*)ctr;
    while (*p != target) __nanosleep(32);
}

__global__ void __launch_bounds__(256, 4)
fused_kernel(const float* __restrict__ x,
             const float* __restrict__ Wv,
             const float* __restrict__ bv,
             float* __restrict__ out) {
    __shared__ float xbs[DD];           // xbar for this block's batch
    __shared__ float red[8][64];        // GEMM slice-reduce (8 d-slices)

    const int j = blockIdx.x;           // 0..36
    const int b = blockIdx.y;           // 0..7
    const int t = threadIdx.x;

    // ======================= Stage 1: column sum of x ======================
    {
        const int d  = t * 4;
        const int r0 = (j * SS) / NCHUNK;
        const int r1 = ((j + 1) * SS) / NCHUNK;
        const int n  = r1 - r0;         // 55 or 56 rows

        const float4* xp = reinterpret_cast<const float4*>(
            x + ((size_t)(b * SS + r0)) * DD + d);
        const size_t rs = DD / 4;

        float4 a0 = make_float4(0.f, 0.f, 0.f, 0.f);
        float4 a1 = make_float4(0.f, 0.f, 0.f, 0.f);
        float4 a2 = make_float4(0.f, 0.f, 0.f, 0.f);
        float4 a3 = make_float4(0.f, 0.f, 0.f, 0.f);

        int s = 0;
        for (; s + 8 <= n; s += 8, xp += 8 * rs) {
            const float4 v0 = xp[0 * rs];
            const float4 v1 = xp[1 * rs];
            const float4 v2 = xp[2 * rs];
            const float4 v3 = xp[3 * rs];
            const float4 v4 = xp[4 * rs];
            const float4 v5 = xp[5 * rs];
            const float4 v6 = xp[6 * rs];
            const float4 v7 = xp[7 * rs];
            a0.x += v0.x; a0.y += v0.y; a0.z += v0.z; a0.w += v0.w;
            a1.x += v1.x; a1.y += v1.y; a1.z += v1.z; a1.w += v1.w;
            a2.x += v2.x; a2.y += v2.y; a2.z += v2.z; a2.w += v2.w;
            a3.x += v3.x; a3.y += v3.y; a3.z += v3.z; a3.w += v3.w;
            a0.x += v4.x; a0.y += v4.y; a0.z += v4.z; a0.w += v4.w;
            a1.x += v5.x; a1.y += v5.y; a1.z += v5.z; a1.w += v5.w;
            a2.x += v6.x; a2.y += v6.y; a2.z += v6.z; a2.w += v6.w;
            a3.x += v7.x; a3.y += v7.y; a3.z += v7.z; a3.w += v7.w;
        }
        for (; s < n; s++, xp += rs) {
            const float4 v = *xp;
            a0.x += v.x; a0.y += v.y; a0.z += v.z; a0.w += v.w;
        }
        a0.x += a1.x; a0.y += a1.y; a0.z += a1.z; a0.w += a1.w;
        a2.x += a3.x; a2.y += a3.y; a2.z += a3.z; a2.w += a3.w;
        a0.x += a2.x; a0.y += a2.y; a0.z += a2.z; a0.w += a2.w;

        *reinterpret_cast<float4*>(
            g_partial + ((size_t)(b * NCHUNK + j)) * DD + d) = a0;
    }
    __syncthreads();
    __threadfence();                    // release partials
    if (t == 0) atomicAdd(&g_cb[b], 1u);

    if (j >= 8) return;                 // 232 blocks done; 64 continue

    // =============== Wait for THIS batch's 37 partials only ================
    if (t == 0) spin_until(&g_cb[b], NCHUNK);
    __syncthreads();
    __threadfence();                    // acquire

    const int ktile = j;                // k range [64*ktile, 64*ktile+64)
    const int kbase = ktile * 64;

    // ========= Phase A: xbar reduce, 16 loads in flight ====================
    {
        const float4* p = reinterpret_cast<const float4*>(
            g_partial + (size_t)(b * NCHUNK) * DD) + t;
        const size_t cs = DD / 4;

        float4 a0 = make_float4(0.f, 0.f, 0.f, 0.f);
        float4 a1 = make_float4(0.f, 0.f, 0.f, 0.f);
        float4 a2 = make_float4(0.f, 0.f, 0.f, 0.f);
        float4 a3 = make_float4(0.f, 0.f, 0.f, 0.f);
        int c = 0;
        for (; c + 16 <= NCHUNK; c += 16) {
            float4 v[16];
#pragma unroll
            for (int i = 0; i < 16; i++)
                v[i] = p[(size_t)(c + i) * cs];
#pragma unroll
            for (int i = 0; i < 16; i += 4) {
                a0.x += v[i+0].x; a0.y += v[i+0].y; a0.z += v[i+0].z; a0.w += v[i+0].w;
                a1.x += v[i+1].x; a1.y += v[i+1].y; a1.z += v[i+1].z; a1.w += v[i+1].w;
                a2.x += v[i+2].x; a2.y += v[i+2].y; a2.z += v[i+2].z; a2.w += v[i+2].w;
                a3.x += v[i+3].x; a3.y += v[i+3].y; a3.z += v[i+3].z; a3.w += v[i+3].w;
            }
        }
        for (; c + 8 <= NCHUNK; c += 8) {
            float4 v[8];
#pragma unroll
            for (int i = 0; i < 8; i++)
                v[i] = p[(size_t)(c + i) * cs];
#pragma unroll
            for (int i = 0; i < 8; i += 4) {
                a0.x += v[i+0].x; a0.y += v[i+0].y; a0.z += v[i+0].z; a0.w += v[i+0].w;
                a1.x += v[i+1].x; a1.y += v[i+1].y; a1.z += v[i+1].z; a1.w += v[i+1].w;
                a2.x += v[i+2].x; a2.y += v[i+2].y; a2.z += v[i+2].z; a2.w += v[i+2].w;
                a3.x += v[i+3].x; a3.y += v[i+3].y; a3.z += v[i+3].z; a3.w += v[i+3].w;
            }
        }
        for (; c < NCHUNK; c++) {
            const float4 v = p[(size_t)c * cs];
            a0.x += v.x; a0.y += v.y; a0.z += v.z; a0.w += v.w;
        }
        a0.x += a1.x; a0.y += a1.y; a0.z += a1.z; a0.w += a1.w;
        a2.x += a3.x; a2.y += a3.y; a2.z += a3.z; a2.w += a3.w;
        a0.x += a2.x; a0.y += a2.y; a0.z += a2.z; a0.w += a2.w;

        const float inv = 1.0f / (float)SS;
        a0.x *= inv; a0.y *= inv; a0.z *= inv; a0.w *= inv;
        reinterpret_cast<float4*>(xbs)[t] = a0;
    }
    __syncthreads();

    // ===== Phase B: thread owns a k-pair + 128-d slice; 4 load rounds ======
    {
        const int kp  = (t & 31) * 2;   // k pair within tile (0,2,..,62)
        const int dsl = t >> 5;         // 0..7, 128 d each
        const int d0  = dsl * 128;

        float2 c0 = make_float2(0.f, 0.f);
        float2 c1 = make_float2(0.f, 0.f);
        float2 c2 = make_float2(0.f, 0.f);
        float2 c3 = make_float2(0.f, 0.f);
#pragma unroll
        for (int g = 0; g < 4; g++) {
            const int dg = d0 + g * 32;
            float2 w[32];
#pragma unroll
            for (int i = 0; i < 32; i++)
                w[i] = *reinterpret_cast<const float2*>(
                    Wv + (size_t)(dg + i) * DKK + kbase + kp);
#pragma unroll
            for (int i = 0; i < 32; i += 4) {
                const float x0 = xbs[dg + i + 0];
                const float x1 = xbs[dg + i + 1];
                const float x2 = xbs[dg + i + 2];
                const float x3 = xbs[dg + i + 3];
                c0.x += w[i+0].x * x0; c0.y += w[i+0].y * x0;
                c1.x += w[i+1].x * x1; c1.y += w[i+1].y * x1;
                c2.x += w[i+2].x * x2; c2.y += w[i+2].y * x2;
                c3.x += w[i+3].x * x3; c3.y += w[i+3].y * x3;
            }
        }
        red[dsl][kp]     = (c0.x + c1.x) + (c2.x + c3.x);
        red[dsl][kp + 1] = (c0.y + c1.y) + (c2.y + c3.y);
    }
    __syncthreads();

    if (t < 64) {
        float s = bv[kbase + t];
#pragma unroll
        for (int i = 0; i < 8; i++)
            s += red[i][t];
        out[(size_t)b * DKK + kbase + t] = s;
    }

    // ================= Counter reset (last consumer block) =================
    __syncthreads();
    if (t == 0) {
        const unsigned old = atomicAdd(&g_done, 1u);
        if (old == 63u) {               // all 64 consumer blocks finished
#pragma unroll
            for (int i = 0; i < BB; i++) g_cb[i] = 0;
            g_done = 0;
            __threadfence();
        }
    }
}

// ---------------------------------------------------------------------------
// Inputs (metadata order): x, Wq, bq, Wk, bk, Wv, bv
// ---------------------------------------------------------------------------
extern "C" void kernel_launch(void* const* d_in, const int* in_sizes, int n_in,
                              void* d_out, int out_size) {
    const float* x  = (const float*)d_in[0];
    const float* Wv = (const float*)d_in[5];
    const float* bv = (const float*)d_in[6];
    float* out = (float*)d_out;

    fused_kernel<<<dim3(NCHUNK, BB), 256>>>(x, Wv, bv, out);
}